// round 7
// baseline (speedup 1.0000x reference)
#include <cuda_runtime.h>
#include <cuda_bf16.h>
#include <math.h>
#include <float.h>
#include <stdint.h>

#define Dd   2048
#define Hh   16
#define HD   128
#define HALF 64
#define FFd  8192
#define Bb   4
#define Ss   2048
#define KK   1024
#define MTOT (Bb * KK)
#define BH   (Bb * Hh)
#define EPSf 1e-6f
#define SM_SCALE 0.08838834764831843f

typedef __nv_bfloat16 bf16;

// ----------------------------------------------------------------------------
// Scratch (device globals)
// ----------------------------------------------------------------------------
__device__ float g_weights[Bb * Ss];
__device__ int   g_kidx[MTOT];
__device__ int   g_kpos[MTOT];
__device__ float g_X  [(size_t)MTOT * Dd];
__device__ float g_q  [(size_t)MTOT * Dd];
__device__ float g_k  [(size_t)MTOT * Dd];
__device__ float g_v  [(size_t)MTOT * Dd];
__device__ float g_scores[(size_t)BH * KK * KK];
__device__ float g_ao [(size_t)MTOT * Dd];
__device__ float g_delta[(size_t)MTOT * Dd];

// split bf16 operand buffers
__device__ bf16 g_h1hi[(size_t)MTOT * Dd],  g_h1lo[(size_t)MTOT * Dd];
__device__ bf16 g_qhi [(size_t)MTOT * Dd],  g_qlo [(size_t)MTOT * Dd];
__device__ bf16 g_khi [(size_t)MTOT * Dd],  g_klo [(size_t)MTOT * Dd];
__device__ bf16 g_vThi[(size_t)BH * HD * KK], g_vTlo[(size_t)BH * HD * KK];
__device__ bf16 g_phi [(size_t)BH * KK * KK], g_plo [(size_t)BH * KK * KK];
__device__ bf16 g_atthi[(size_t)MTOT * Dd], g_attlo[(size_t)MTOT * Dd];
__device__ bf16 g_h2nhi[(size_t)MTOT * Dd], g_h2nlo[(size_t)MTOT * Dd];
__device__ bf16 g_ffhhi[(size_t)MTOT * FFd], g_ffhlo[(size_t)MTOT * FFd];
// split transposed weights [N][K]
__device__ bf16 g_WqThi[(size_t)Dd * Dd], g_WqTlo[(size_t)Dd * Dd];
__device__ bf16 g_WkThi[(size_t)Dd * Dd], g_WkTlo[(size_t)Dd * Dd];
__device__ bf16 g_WvThi[(size_t)Dd * Dd], g_WvTlo[(size_t)Dd * Dd];
__device__ bf16 g_WoThi[(size_t)Dd * Dd], g_WoTlo[(size_t)Dd * Dd];
__device__ bf16 g_W1Thi[(size_t)FFd * Dd], g_W1Tlo[(size_t)FFd * Dd];
__device__ bf16 g_W2Thi[(size_t)Dd * FFd], g_W2Tlo[(size_t)Dd * FFd];

// ----------------------------------------------------------------------------
// Helpers
// ----------------------------------------------------------------------------
__device__ __forceinline__ float warpReduceSum(float v) {
#pragma unroll
    for (int o = 16; o > 0; o >>= 1) v += __shfl_xor_sync(0xffffffffu, v, o);
    return v;
}
__device__ __forceinline__ float warpReduceMax(float v) {
#pragma unroll
    for (int o = 16; o > 0; o >>= 1) v = fmaxf(v, __shfl_xor_sync(0xffffffffu, v, o));
    return v;
}
__device__ float blockReduceSum(float v) {
    __shared__ float sm[8];
    __shared__ float res;
    int lane = threadIdx.x & 31, w = threadIdx.x >> 5;
    int nw = (blockDim.x + 31) >> 5;
    v = warpReduceSum(v);
    if (lane == 0) sm[w] = v;
    __syncthreads();
    if (w == 0) {
        float x = (lane < nw) ? sm[lane] : 0.f;
        x = warpReduceSum(x);
        if (lane == 0) res = x;
    }
    __syncthreads();
    return res;
}
__device__ float blockReduceMax(float v) {
    __shared__ float sm[8];
    __shared__ float res;
    int lane = threadIdx.x & 31, w = threadIdx.x >> 5;
    int nw = (blockDim.x + 31) >> 5;
    v = warpReduceMax(v);
    if (lane == 0) sm[w] = v;
    __syncthreads();
    if (w == 0) {
        float x = (lane < nw) ? sm[lane] : -FLT_MAX;
        x = warpReduceMax(x);
        if (lane == 0) res = x;
    }
    __syncthreads();
    return res;
}
__device__ __forceinline__ float gelu_tanh(float x) {
    float x3 = x * x * x;
    float t = tanhf(0.7978845608028654f * (x + 0.044715f * x3));
    return 0.5f * x * (1.f + t);
}
__device__ __forceinline__ uint32_t smem_u32(const void* p) {
    uint32_t a;
    asm("{ .reg .u64 t; cvta.to.shared.u64 t, %1; cvt.u32.u64 %0, t; }" : "=r"(a) : "l"(p));
    return a;
}
__device__ __forceinline__ void cvt_hilo(float a, float b, uint32_t& h, uint32_t& l) {
    __nv_bfloat162 hv = __floats2bfloat162_rn(a, b);
    h = *reinterpret_cast<uint32_t*>(&hv);
    float fa = __uint_as_float(h << 16);
    float fb = __uint_as_float(h & 0xffff0000u);
    __nv_bfloat162 lv = __floats2bfloat162_rn(a - fa, b - fb);
    l = *reinterpret_cast<uint32_t*>(&lv);
}
__device__ __forceinline__ void store_hilo(bf16* H, bf16* L, size_t i, float v) {
    bf16 h = __float2bfloat16(v);
    H[i] = h;
    L[i] = __float2bfloat16(v - __bfloat162float(h));
}

// ----------------------------------------------------------------------------
// HMMA / cp.async primitives (base PTX, sm_80+)
// ----------------------------------------------------------------------------
__device__ __forceinline__ void ldsm4(uint32_t* r, uint32_t a) {
    asm volatile("ldmatrix.sync.aligned.m8n8.x4.shared.b16 {%0,%1,%2,%3}, [%4];"
        : "=r"(r[0]), "=r"(r[1]), "=r"(r[2]), "=r"(r[3]) : "r"(a));
}
__device__ __forceinline__ void ldsm2(uint32_t* r, uint32_t a) {
    asm volatile("ldmatrix.sync.aligned.m8n8.x2.shared.b16 {%0,%1}, [%2];"
        : "=r"(r[0]), "=r"(r[1]) : "r"(a));
}
__device__ __forceinline__ void mma16816(float* c, const uint32_t* a, const uint32_t* b) {
    asm volatile("mma.sync.aligned.m16n8k16.row.col.f32.bf16.bf16.f32 "
        "{%0,%1,%2,%3}, {%4,%5,%6,%7}, {%8,%9}, {%0,%1,%2,%3};"
        : "+f"(c[0]), "+f"(c[1]), "+f"(c[2]), "+f"(c[3])
        : "r"(a[0]), "r"(a[1]), "r"(a[2]), "r"(a[3]), "r"(b[0]), "r"(b[1]));
}
__device__ __forceinline__ void cp16(uint32_t s, const void* g) {
    asm volatile("cp.async.cg.shared.global [%0], [%1], 16;" :: "r"(s), "l"(g));
}
#define CP_COMMIT() asm volatile("cp.async.commit_group;" ::: "memory")
#define CP_WAIT2()  asm volatile("cp.async.wait_group 2;" ::: "memory")

// SMEM: 4 tiles (Ahi,Alo,Bhi,Blo) of 128 rows x 32 bf16, rows padded to 80B
#define ROWB    80
#define TILE_B  10240
#define STAGE_B 40960
#define NSTAGE  4
#define HG_SMEM (NSTAGE * STAGE_B)

// ----------------------------------------------------------------------------
// Split-bf16 HMMA GEMM body: C[128x128 tile] = A @ B^T with A=Ah+Al, B=Bh+Bl
// 256 thr = 8 warps (2x4), warp tile 64x32, BK=32, 4-stage cp.async pipeline.
// mode: 0 = fp32 C; 1 = fp32 C += Add; 2 = gelu -> Chi/Clo; 3 = Chi/Clo
// ----------------------------------------------------------------------------
__device__ __forceinline__ void hg_body(
    const bf16* __restrict__ Ahi, const bf16* __restrict__ Alo, int lda,
    const bf16* __restrict__ Bhi, const bf16* __restrict__ Blo, int ldb,
    float* __restrict__ C, const float* __restrict__ Add,
    bf16* __restrict__ Chi, bf16* __restrict__ Clo,
    int ldc, int Kd, int mode)
{
    extern __shared__ char smc[];
    const uint32_t sbase = smem_u32(smc);
    const int tid  = threadIdx.x;
    const int m0   = blockIdx.y * 128, n0 = blockIdx.x * 128;
    const int wid  = tid >> 5, lane = tid & 31;
    const int wm   = (wid >> 2) * 64;
    const int wn   = (wid & 3) * 32;

    // cp.async mapping: tile t4 (0=Ahi 1=Alo 2=Bhi 3=Blo), 2 rows per thread
    const int t4 = tid >> 6;
    const int r2 = (tid & 63) * 2;
    const bf16* gsrc;
    int gld;
    if      (t4 == 0) { gsrc = Ahi + (size_t)(m0 + r2) * lda; gld = lda; }
    else if (t4 == 1) { gsrc = Alo + (size_t)(m0 + r2) * lda; gld = lda; }
    else if (t4 == 2) { gsrc = Bhi + (size_t)(n0 + r2) * ldb; gld = ldb; }
    else              { gsrc = Blo + (size_t)(n0 + r2) * ldb; gld = ldb; }
    const uint32_t sdst0 = sbase + t4 * TILE_B + r2 * ROWB;

    // ldmatrix lane addressing
    const int a_row = (lane & 7) + ((lane >> 3) & 1) * 8;
    const int a_cb  = (lane >> 4) * 16;
    const int ll    = lane & 15;
    const int b_row = ll & 7;
    const int b_cb  = (ll >> 3) * 16;

    float acc[4][4][4];
#pragma unroll
    for (int i = 0; i < 4; i++)
#pragma unroll
        for (int j = 0; j < 4; j++)
#pragma unroll
            for (int r = 0; r < 4; r++) acc[i][j][r] = 0.f;

    const int nch = Kd >> 5;

#define HG_ISSUE(cc) do {                                                   \
        uint32_t sd = sdst0 + ((cc) & (NSTAGE - 1)) * STAGE_B;              \
        const char* gp = (const char*)gsrc + ((cc) << 6);                   \
        _Pragma("unroll")                                                   \
        for (int rr = 0; rr < 2; rr++)                                      \
            _Pragma("unroll")                                               \
            for (int ch = 0; ch < 4; ch++)                                  \
                cp16(sd + rr * ROWB + ch * 16,                              \
                     gp + (size_t)rr * gld * 2 + ch * 16);                  \
    } while (0)

    int pf = 0;
    for (; pf < 3 && pf < nch; pf++) { HG_ISSUE(pf); CP_COMMIT(); }

    for (int c = 0; c < nch; c++) {
        CP_WAIT2();
        __syncthreads();
        const uint32_t sb = sbase + (c & (NSTAGE - 1)) * STAGE_B;
#pragma unroll
        for (int ks = 0; ks < 2; ks++) {
            const int kb = ks * 32;
            uint32_t ahi4[4][4], alo4[4][4];
#pragma unroll
            for (int mf = 0; mf < 4; mf++) {
                uint32_t ad = sb + (wm + mf * 16 + a_row) * ROWB + kb + a_cb;
                ldsm4(ahi4[mf], ad);
                ldsm4(alo4[mf], ad + TILE_B);
            }
            uint32_t bhi2[4][2], blo2[4][2];
#pragma unroll
            for (int nf = 0; nf < 4; nf++) {
                uint32_t bd = sb + 2 * TILE_B + (wn + nf * 8 + b_row) * ROWB + kb + b_cb;
                ldsm2(bhi2[nf], bd);
                ldsm2(blo2[nf], bd + TILE_B);
            }
#pragma unroll
            for (int mf = 0; mf < 4; mf++)
#pragma unroll
                for (int nf = 0; nf < 4; nf++) {
                    mma16816(acc[mf][nf], ahi4[mf], bhi2[nf]);
                    mma16816(acc[mf][nf], ahi4[mf], blo2[nf]);
                    mma16816(acc[mf][nf], alo4[mf], bhi2[nf]);
                }
        }
        __syncthreads();
        if (pf < nch) { HG_ISSUE(pf); pf++; }
        CP_COMMIT();
    }
#undef HG_ISSUE

    // epilogue
#pragma unroll
    for (int mf = 0; mf < 4; mf++) {
        int rbase = m0 + wm + mf * 16 + (lane >> 2);
#pragma unroll
        for (int nf = 0; nf < 4; nf++) {
            int cb = n0 + wn + nf * 8 + (lane & 3) * 2;
#pragma unroll
            for (int hlf = 0; hlf < 2; hlf++) {
                int row = rbase + hlf * 8;
                float vx = acc[mf][nf][hlf * 2];
                float vy = acc[mf][nf][hlf * 2 + 1];
                if (mode == 1) {
                    const float* ap = Add + (size_t)row * ldc + cb;
                    vx += ap[0]; vy += ap[1];
                }
                if (mode == 2) { vx = gelu_tanh(vx); vy = gelu_tanh(vy); }
                if (mode <= 1) {
                    *(float2*)&C[(size_t)row * ldc + cb] = make_float2(vx, vy);
                } else {
                    uint32_t h, l;
                    cvt_hilo(vx, vy, h, l);
                    *(uint32_t*)&Chi[(size_t)row * ldc + cb] = h;
                    *(uint32_t*)&Clo[(size_t)row * ldc + cb] = l;
                }
            }
        }
    }
}

// Wrappers
__global__ void __launch_bounds__(256) k_hg(
    const bf16* Ahi, const bf16* Alo, int lda,
    const bf16* Bhi, const bf16* Blo, int ldb,
    float* C, const float* Add, bf16* Chi, bf16* Clo, int ldc,
    int Kd, int mode)
{
    hg_body(Ahi, Alo, lda, Bhi, Blo, ldb, C, Add, Chi, Clo, ldc, Kd, mode);
}

__global__ void __launch_bounds__(256) k_hg_scores() {
    if (blockIdx.x * 128 > blockIdx.y * 128 + 127) return;  // fully masked tile
    int z = blockIdx.z;
    int b = z >> 4, h = z & 15;
    size_t qo = (size_t)b * KK * Dd + (size_t)h * HD;
    hg_body(g_qhi + qo, g_qlo + qo, Dd, g_khi + qo, g_klo + qo, Dd,
            g_scores + (size_t)z * KK * KK, nullptr, nullptr, nullptr,
            KK, HD, 0);
}

__global__ void __launch_bounds__(256) k_hg_av() {
    int z = blockIdx.z;
    int b = z >> 4, h = z & 15;
    size_t po = (size_t)z * KK * KK;
    size_t vo = (size_t)z * HD * KK;
    size_t co = (size_t)b * KK * Dd + (size_t)h * HD;
    hg_body(g_phi + po, g_plo + po, KK, g_vThi + vo, g_vTlo + vo, KK,
            nullptr, nullptr, g_atthi + co, g_attlo + co, Dd, KK, 3);
}

// ----------------------------------------------------------------------------
// Weight transpose + split: W[K][N] fp32 -> Thi/Tlo[N][K] bf16
// ----------------------------------------------------------------------------
__global__ void k_tsplit(const float* __restrict__ W, bf16* __restrict__ Thi,
                         bf16* __restrict__ Tlo, int Kd, int Nd) {
    __shared__ float t[32][33];
    int k0 = blockIdx.y * 32, n0 = blockIdx.x * 32;
    int x = threadIdx.x, y = threadIdx.y;
#pragma unroll
    for (int i = 0; i < 32; i += 8)
        t[y + i][x] = W[(size_t)(k0 + y + i) * Nd + n0 + x];
    __syncthreads();
#pragma unroll
    for (int i = 0; i < 32; i += 8)
        store_hilo(Thi, Tlo, (size_t)(n0 + y + i) * Kd + k0 + x, t[x][y + i]);
}

__global__ void k_vt() {   // g_v [b][tok][h][d] -> vThi/lo [b*H+h][d][tok]
    __shared__ float t[32][33];
    int z = blockIdx.z, b = z >> 4, h = z & 15;
    int tok0 = blockIdx.x * 32, d0 = blockIdx.y * 32;
    int x = threadIdx.x, y = threadIdx.y;
#pragma unroll
    for (int i = 0; i < 32; i += 8)
        t[y + i][x] = g_v[(size_t)b * KK * Dd + (size_t)(tok0 + y + i) * Dd + h * HD + d0 + x];
    __syncthreads();
#pragma unroll
    for (int i = 0; i < 32; i += 8)
        store_hilo(g_vThi, g_vTlo,
                   (size_t)z * HD * KK + (size_t)(d0 + y + i) * KK + tok0 + x,
                   t[x][y + i]);
}

// ----------------------------------------------------------------------------
// Router / select / gather
// ----------------------------------------------------------------------------
__global__ void k_router(const float* __restrict__ hidden, const float* __restrict__ rw) {
    int wid  = (blockIdx.x * blockDim.x + threadIdx.x) >> 5;
    int lane = threadIdx.x & 31;
    if (wid >= Bb * Ss) return;
    const float4* x  = (const float4*)(hidden + (size_t)wid * Dd);
    const float4* r4 = (const float4*)rw;
    float s = 0.f;
#pragma unroll 4
    for (int i = lane; i < Dd / 4; i += 32) {
        float4 a = x[i], b = r4[i];
        s += a.x * b.x + a.y * b.y + a.z * b.z + a.w * b.w;
    }
    s = warpReduceSum(s);
    if (lane == 0) g_weights[wid] = 1.f / (1.f + expf(-s));
}

__global__ void k_select(const int* __restrict__ pos_ids) {
    __shared__ float w[Ss];
    __shared__ unsigned char sel[Ss];
    int b = blockIdx.x;
    for (int s = threadIdx.x; s < Ss; s += blockDim.x) w[s] = g_weights[b * Ss + s];
    __syncthreads();
    for (int s = threadIdx.x; s < Ss; s += blockDim.x) {
        float ws = w[s];
        int r = 0;
        for (int t = 0; t < Ss; t++) {
            float wt = w[t];
            r += (wt > ws) || (wt == ws && t < s);
        }
        sel[s] = (r < KK) ? 1 : 0;
    }
    __syncthreads();
    for (int s = threadIdx.x; s < Ss; s += blockDim.x) {
        if (sel[s]) {
            int j = 0;
            for (int t = 0; t < s; t++) j += sel[t];
            g_kidx[b * KK + j] = s;
            g_kpos[b * KK + j] = pos_ids[s];
        }
    }
}

__global__ void k_gather_rms1(const float* __restrict__ hidden, const float* __restrict__ ln1w) {
    int t = blockIdx.x;
    int b = t >> 10;
    int s = g_kidx[t];
    const float* src = hidden + ((size_t)(b * Ss + s)) * Dd;
    float* xdst = g_X + (size_t)t * Dd;
    size_t hb = (size_t)t * Dd;
    float loc[8];
    float ss = 0.f;
#pragma unroll
    for (int i = 0; i < 8; i++) {
        float v = src[threadIdx.x + i * 256];
        loc[i] = v;
        ss += v * v;
    }
    ss = blockReduceSum(ss);
    float r = rsqrtf(ss * (1.f / Dd) + EPSf);
#pragma unroll
    for (int i = 0; i < 8; i++) {
        int c = threadIdx.x + i * 256;
        xdst[c] = loc[i];
        store_hilo(g_h1hi, g_h1lo, hb + c, loc[i] * r * ln1w[c]);
    }
}

// ----------------------------------------------------------------------------
// RoPE: q,k fp32 -> rotated, split to hi/lo bf16
// ----------------------------------------------------------------------------
__global__ void k_rope() {
    int t = blockIdx.x * blockDim.x + threadIdx.x;
    if (t >= MTOT * Hh * HALF) return;
    int d   = t & 63;
    int th  = t >> 6;
    int h   = th & 15;
    int tok = th >> 4;
    int pos = g_kpos[tok];
    float freq = (float)exp(-(double)d * (1.0 / 64.0) * 9.210340371976184);
    float ang  = (float)pos * freq;
    float c = cosf(ang), s = sinf(ang);
    size_t base = (size_t)tok * Dd + h * HD + d;
    float q1 = g_q[base], q2 = g_q[base + HALF];
    store_hilo(g_qhi, g_qlo, base,        q1 * c - q2 * s);
    store_hilo(g_qhi, g_qlo, base + HALF, q2 * c + q1 * s);
    float k1 = g_k[base], k2 = g_k[base + HALF];
    store_hilo(g_khi, g_klo, base,        k1 * c - k2 * s);
    store_hilo(g_khi, g_klo, base + HALF, k2 * c + k1 * s);
}

// ----------------------------------------------------------------------------
// Softmax: scores fp32 -> probs hi/lo bf16
// ----------------------------------------------------------------------------
__global__ void k_softmax() {
    int row = blockIdx.x;
    int q = row & (KK - 1);
    const float* r = g_scores + (size_t)row * KK;
    size_t ob = (size_t)row * KK;
    int n = q + 1;
    float m = -FLT_MAX;
    for (int i = threadIdx.x; i < n; i += blockDim.x) m = fmaxf(m, r[i]);
    m = blockReduceMax(m);
    float sum = 0.f;
    for (int i = threadIdx.x; i < n; i += blockDim.x) sum += expf(SM_SCALE * (r[i] - m));
    sum = blockReduceSum(sum);
    float inv = 1.f / sum;
    for (int i = threadIdx.x; i < KK; i += blockDim.x) {
        float v = 0.f;
        if (i < n) v = expf(SM_SCALE * (r[i] - m)) * inv;
        store_hilo(g_phi, g_plo, ob + i, v);
    }
}

// ----------------------------------------------------------------------------
// h2 = X + ao ; rmsnorm -> hi/lo
// ----------------------------------------------------------------------------
__global__ void k_h2rms(const float* __restrict__ ln2w) {
    int t = blockIdx.x;
    const float* xa = g_X  + (size_t)t * Dd;
    const float* ao = g_ao + (size_t)t * Dd;
    size_t ob = (size_t)t * Dd;
    float loc[8];
    float ss = 0.f;
#pragma unroll
    for (int i = 0; i < 8; i++) {
        int c = threadIdx.x + i * 256;
        float v = xa[c] + ao[c];
        loc[i] = v;
        ss += v * v;
    }
    ss = blockReduceSum(ss);
    float r = rsqrtf(ss * (1.f / Dd) + EPSf);
#pragma unroll
    for (int i = 0; i < 8; i++) {
        int c = threadIdx.x + i * 256;
        store_hilo(g_h2nhi, g_h2nlo, ob + c, loc[i] * r * ln2w[c]);
    }
}

__global__ void k_outscale(const float* __restrict__ hidden, float* __restrict__ out) {
    size_t total4 = (size_t)Bb * Ss * Dd / 4;
    for (size_t i = (size_t)blockIdx.x * blockDim.x + threadIdx.x; i < total4;
         i += (size_t)gridDim.x * blockDim.x) {
        size_t tok = (i * 4) >> 11;
        float sc = g_weights[tok];
        float4 h = ((const float4*)hidden)[i];
        h.x *= sc; h.y *= sc; h.z *= sc; h.w *= sc;
        ((float4*)out)[i] = h;
    }
}

__global__ void k_scatter(float* __restrict__ out) {
    int t = blockIdx.x;
    int b = t >> 10;
    int s = g_kidx[t];
    int tok = b * Ss + s;
    float sc = g_weights[tok];
    float*       o  = out     + (size_t)tok * Dd;
    const float* dl = g_delta + (size_t)t * Dd;
    const float* xk = g_X     + (size_t)t * Dd;
    for (int c = threadIdx.x; c < Dd; c += blockDim.x)
        o[c] = dl[c] * sc + xk[c];
}

// ----------------------------------------------------------------------------
// Launch
// ----------------------------------------------------------------------------
extern "C" void kernel_launch(void* const* d_in, const int* in_sizes, int n_in,
                              void* d_out, int out_size) {
    const float* hidden   = (const float*)d_in[0];
    const int*   pos_ids  = (const int*)d_in[1];
    const float* router_w = (const float*)d_in[4];
    const float* ln1w     = (const float*)d_in[5];
    const float* ln2w     = (const float*)d_in[6];
    const float* Wq       = (const float*)d_in[7];
    const float* Wk       = (const float*)d_in[8];
    const float* Wv       = (const float*)d_in[9];
    const float* Wo       = (const float*)d_in[10];
    const float* W1       = (const float*)d_in[11];
    const float* W2       = (const float*)d_in[12];
    float* out = (float*)d_out;

    cudaFuncSetAttribute(k_hg,        cudaFuncAttributeMaxDynamicSharedMemorySize, HG_SMEM);
    cudaFuncSetAttribute(k_hg_scores, cudaFuncAttributeMaxDynamicSharedMemorySize, HG_SMEM);
    cudaFuncSetAttribute(k_hg_av,     cudaFuncAttributeMaxDynamicSharedMemorySize, HG_SMEM);

#define SYM(p, g) cudaGetSymbolAddress((void**)&p, g)
    bf16 *WqThi, *WqTlo, *WkThi, *WkTlo, *WvThi, *WvTlo, *WoThi, *WoTlo;
    bf16 *W1Thi, *W1Tlo, *W2Thi, *W2Tlo;
    bf16 *h1hi, *h1lo, *atthi, *attlo, *h2nhi, *h2nlo, *ffhhi, *ffhlo;
    float *q, *k, *v, *ao, *dlt, *scores;
    SYM(WqThi, g_WqThi); SYM(WqTlo, g_WqTlo);
    SYM(WkThi, g_WkThi); SYM(WkTlo, g_WkTlo);
    SYM(WvThi, g_WvThi); SYM(WvTlo, g_WvTlo);
    SYM(WoThi, g_WoThi); SYM(WoTlo, g_WoTlo);
    SYM(W1Thi, g_W1Thi); SYM(W1Tlo, g_W1Tlo);
    SYM(W2Thi, g_W2Thi); SYM(W2Tlo, g_W2Tlo);
    SYM(h1hi, g_h1hi);   SYM(h1lo, g_h1lo);
    SYM(atthi, g_atthi); SYM(attlo, g_attlo);
    SYM(h2nhi, g_h2nhi); SYM(h2nlo, g_h2nlo);
    SYM(ffhhi, g_ffhhi); SYM(ffhlo, g_ffhlo);
    SYM(q, g_q); SYM(k, g_k); SYM(v, g_v);
    SYM(ao, g_ao); SYM(dlt, g_delta); SYM(scores, g_scores);
#undef SYM

    dim3 tb(32, 8);
    k_tsplit<<<dim3(Dd / 32, Dd / 32), tb>>>(Wq, WqThi, WqTlo, Dd, Dd);
    k_tsplit<<<dim3(Dd / 32, Dd / 32), tb>>>(Wk, WkThi, WkTlo, Dd, Dd);
    k_tsplit<<<dim3(Dd / 32, Dd / 32), tb>>>(Wv, WvThi, WvTlo, Dd, Dd);
    k_tsplit<<<dim3(Dd / 32, Dd / 32), tb>>>(Wo, WoThi, WoTlo, Dd, Dd);
    k_tsplit<<<dim3(FFd / 32, Dd / 32), tb>>>(W1, W1Thi, W1Tlo, Dd, FFd);
    k_tsplit<<<dim3(Dd / 32, FFd / 32), tb>>>(W2, W2Thi, W2Tlo, FFd, Dd);

    k_router<<<(Bb * Ss) / 8, 256>>>(hidden, router_w);
    k_select<<<Bb, 1024>>>(pos_ids);
    k_gather_rms1<<<MTOT, 256>>>(hidden, ln1w);

    dim3 gD(Dd / 128, MTOT / 128);
    k_hg<<<gD, 256, HG_SMEM>>>(h1hi, h1lo, Dd, WqThi, WqTlo, Dd,
                               q, nullptr, nullptr, nullptr, Dd, Dd, 0);
    k_hg<<<gD, 256, HG_SMEM>>>(h1hi, h1lo, Dd, WkThi, WkTlo, Dd,
                               k, nullptr, nullptr, nullptr, Dd, Dd, 0);
    k_hg<<<gD, 256, HG_SMEM>>>(h1hi, h1lo, Dd, WvThi, WvTlo, Dd,
                               v, nullptr, nullptr, nullptr, Dd, Dd, 0);

    k_rope<<<(MTOT * Hh * HALF + 255) / 256, 256>>>();
    k_vt<<<dim3(KK / 32, HD / 32, BH), tb>>>();
    k_hg_scores<<<dim3(KK / 128, KK / 128, BH), 256, HG_SMEM>>>();
    k_softmax<<<BH * KK, 128>>>();
    k_hg_av<<<dim3(1, KK / 128, BH), 256, HG_SMEM>>>();

    k_hg<<<gD, 256, HG_SMEM>>>(atthi, attlo, Dd, WoThi, WoTlo, Dd,
                               ao, nullptr, nullptr, nullptr, Dd, Dd, 0);
    k_h2rms<<<MTOT, 256>>>(ln2w);
    k_hg<<<dim3(FFd / 128, MTOT / 128), 256, HG_SMEM>>>(
        h2nhi, h2nlo, Dd, W1Thi, W1Tlo, Dd,
        nullptr, nullptr, ffhhi, ffhlo, FFd, Dd, 2);
    k_hg<<<gD, 256, HG_SMEM>>>(ffhhi, ffhlo, FFd, W2Thi, W2Tlo, FFd,
                               dlt, ao, nullptr, nullptr, Dd, FFd, 1);

    k_outscale<<<8192, 256>>>(hidden, out);
    k_scatter<<<MTOT, 256>>>(out);
}

// round 9
// speedup vs baseline: 1.0755x; 1.0755x over previous
#include <cuda_runtime.h>
#include <cuda_bf16.h>
#include <math.h>
#include <float.h>
#include <stdint.h>

#define Dd   2048
#define Hh   16
#define HD   128
#define HALF 64
#define FFd  8192
#define Bb   4
#define Ss   2048
#define KK   1024
#define MTOT (Bb * KK)
#define BH   (Bb * Hh)
#define EPSf 1e-6f
#define SM_SCALE 0.08838834764831843f

typedef __nv_bfloat16 bf16;

// ----------------------------------------------------------------------------
// Scratch (device globals)
// ----------------------------------------------------------------------------
__device__ float g_weights[Bb * Ss];
__device__ int   g_kidx[MTOT];
__device__ int   g_kpos[MTOT];
__device__ float g_X  [(size_t)MTOT * Dd];
__device__ float g_q  [(size_t)MTOT * Dd];
__device__ float g_k  [(size_t)MTOT * Dd];
__device__ float g_v  [(size_t)MTOT * Dd];
__device__ float g_scores[(size_t)BH * KK * KK];
__device__ float g_ao [(size_t)MTOT * Dd];
__device__ float g_delta[(size_t)MTOT * Dd];

// split bf16 operand buffers
__device__ bf16 g_h1hi[(size_t)MTOT * Dd],  g_h1lo[(size_t)MTOT * Dd];
__device__ bf16 g_qhi [(size_t)MTOT * Dd],  g_qlo [(size_t)MTOT * Dd];
__device__ bf16 g_khi [(size_t)MTOT * Dd],  g_klo [(size_t)MTOT * Dd];
__device__ bf16 g_vThi[(size_t)BH * HD * KK], g_vTlo[(size_t)BH * HD * KK];
__device__ bf16 g_phi [(size_t)BH * KK * KK], g_plo [(size_t)BH * KK * KK];
__device__ bf16 g_atthi[(size_t)MTOT * Dd], g_attlo[(size_t)MTOT * Dd];
__device__ bf16 g_h2nhi[(size_t)MTOT * Dd], g_h2nlo[(size_t)MTOT * Dd];
__device__ bf16 g_ffhhi[(size_t)MTOT * FFd], g_ffhlo[(size_t)MTOT * FFd];
// split transposed weights [N][K]
__device__ bf16 g_WqThi[(size_t)Dd * Dd], g_WqTlo[(size_t)Dd * Dd];
__device__ bf16 g_WkThi[(size_t)Dd * Dd], g_WkTlo[(size_t)Dd * Dd];
__device__ bf16 g_WvThi[(size_t)Dd * Dd], g_WvTlo[(size_t)Dd * Dd];
__device__ bf16 g_WoThi[(size_t)Dd * Dd], g_WoTlo[(size_t)Dd * Dd];
__device__ bf16 g_W1Thi[(size_t)FFd * Dd], g_W1Tlo[(size_t)FFd * Dd];
__device__ bf16 g_W2Thi[(size_t)Dd * FFd], g_W2Tlo[(size_t)Dd * FFd];

// ----------------------------------------------------------------------------
// Helpers
// ----------------------------------------------------------------------------
__device__ __forceinline__ float warpReduceSum(float v) {
#pragma unroll
    for (int o = 16; o > 0; o >>= 1) v += __shfl_xor_sync(0xffffffffu, v, o);
    return v;
}
__device__ __forceinline__ float warpReduceMax(float v) {
#pragma unroll
    for (int o = 16; o > 0; o >>= 1) v = fmaxf(v, __shfl_xor_sync(0xffffffffu, v, o));
    return v;
}
__device__ float blockReduceSum(float v) {
    __shared__ float sm[8];
    __shared__ float res;
    int lane = threadIdx.x & 31, w = threadIdx.x >> 5;
    int nw = (blockDim.x + 31) >> 5;
    v = warpReduceSum(v);
    if (lane == 0) sm[w] = v;
    __syncthreads();
    if (w == 0) {
        float x = (lane < nw) ? sm[lane] : 0.f;
        x = warpReduceSum(x);
        if (lane == 0) res = x;
    }
    __syncthreads();
    return res;
}
__device__ float blockReduceMax(float v) {
    __shared__ float sm[8];
    __shared__ float res;
    int lane = threadIdx.x & 31, w = threadIdx.x >> 5;
    int nw = (blockDim.x + 31) >> 5;
    v = warpReduceMax(v);
    if (lane == 0) sm[w] = v;
    __syncthreads();
    if (w == 0) {
        float x = (lane < nw) ? sm[lane] : -FLT_MAX;
        x = warpReduceMax(x);
        if (lane == 0) res = x;
    }
    __syncthreads();
    return res;
}
__device__ __forceinline__ float gelu_tanh(float x) {
    float x3 = x * x * x;
    float t = tanhf(0.7978845608028654f * (x + 0.044715f * x3));
    return 0.5f * x * (1.f + t);
}
__device__ __forceinline__ uint32_t smem_u32(const void* p) {
    uint32_t a;
    asm("{ .reg .u64 t; cvta.to.shared.u64 t, %1; cvt.u32.u64 %0, t; }" : "=r"(a) : "l"(p));
    return a;
}
// fp32 pair -> packed bf16x2 hi + bf16x2 lo
__device__ __forceinline__ void cvt_hilo(float a, float b, uint32_t& h, uint32_t& l) {
    __nv_bfloat162 hv = __floats2bfloat162_rn(a, b);
    h = *reinterpret_cast<uint32_t*>(&hv);
    float fa = __uint_as_float(h << 16);
    float fb = __uint_as_float(h & 0xffff0000u);
    __nv_bfloat162 lv = __floats2bfloat162_rn(a - fa, b - fb);
    l = *reinterpret_cast<uint32_t*>(&lv);
}
__device__ __forceinline__ void store_hilo(bf16* H, bf16* L, size_t i, float v) {
    bf16 h = __float2bfloat16(v);
    H[i] = h;
    L[i] = __float2bfloat16(v - __bfloat162float(h));
}
// split 8 consecutive floats -> uint4 hi + uint4 lo at element index base (even)
__device__ __forceinline__ void store_hilo8(bf16* H, bf16* L, size_t base, const float* v) {
    uint4 hh, ll;
    cvt_hilo(v[0], v[1], hh.x, ll.x);
    cvt_hilo(v[2], v[3], hh.y, ll.y);
    cvt_hilo(v[4], v[5], hh.z, ll.z);
    cvt_hilo(v[6], v[7], hh.w, ll.w);
    *(uint4*)(H + base) = hh;
    *(uint4*)(L + base) = ll;
}

// ----------------------------------------------------------------------------
// HMMA / cp.async primitives (base PTX, sm_80+)
// ----------------------------------------------------------------------------
__device__ __forceinline__ void ldsm4(uint32_t* r, uint32_t a) {
    asm volatile("ldmatrix.sync.aligned.m8n8.x4.shared.b16 {%0,%1,%2,%3}, [%4];"
        : "=r"(r[0]), "=r"(r[1]), "=r"(r[2]), "=r"(r[3]) : "r"(a));
}
__device__ __forceinline__ void ldsm2(uint32_t* r, uint32_t a) {
    asm volatile("ldmatrix.sync.aligned.m8n8.x2.shared.b16 {%0,%1}, [%2];"
        : "=r"(r[0]), "=r"(r[1]) : "r"(a));
}
__device__ __forceinline__ void mma16816(float* c, const uint32_t* a, const uint32_t* b) {
    asm volatile("mma.sync.aligned.m16n8k16.row.col.f32.bf16.bf16.f32 "
        "{%0,%1,%2,%3}, {%4,%5,%6,%7}, {%8,%9}, {%0,%1,%2,%3};"
        : "+f"(c[0]), "+f"(c[1]), "+f"(c[2]), "+f"(c[3])
        : "r"(a[0]), "r"(a[1]), "r"(a[2]), "r"(a[3]), "r"(b[0]), "r"(b[1]));
}
__device__ __forceinline__ void cp16(uint32_t s, const void* g) {
    asm volatile("cp.async.cg.shared.global [%0], [%1], 16;" :: "r"(s), "l"(g));
}
#define CP_COMMIT() asm volatile("cp.async.commit_group;" ::: "memory")
#define CP_WAIT1()  asm volatile("cp.async.wait_group 1;" ::: "memory")
#define CP_WAIT0()  asm volatile("cp.async.wait_group 0;" ::: "memory")

// SMEM: 4 tiles (Ahi,Alo,Bhi,Blo) of 128 rows x 32 bf16, rows padded to 80B
// 2 stages -> 80 KB dynamic smem -> 2 CTAs/SM.
#define ROWB    80
#define TILE_B  10240
#define STAGE_B 40960
#define HG_SMEM (2 * STAGE_B)

// ----------------------------------------------------------------------------
// Split-bf16 HMMA GEMM body: C[128x128 tile] = A @ B^T with A=Ah+Al, B=Bh+Bl
// 256 thr = 8 warps (2x4), warp tile 64x32, BK=32, 2-stage cp.async pipeline.
// mode: 0 = fp32 C; 1 = fp32 C += Add; 2 = gelu -> Chi/Clo; 3 = Chi/Clo
// ----------------------------------------------------------------------------
__device__ __forceinline__ void hg_body(
    const bf16* __restrict__ Ahi, const bf16* __restrict__ Alo, int lda,
    const bf16* __restrict__ Bhi, const bf16* __restrict__ Blo, int ldb,
    float* __restrict__ C, const float* __restrict__ Add,
    bf16* __restrict__ Chi, bf16* __restrict__ Clo,
    int ldc, int Kd, int mode)
{
    extern __shared__ char smc[];
    const uint32_t sbase = smem_u32(smc);
    const int tid  = threadIdx.x;
    const int m0   = blockIdx.y * 128, n0 = blockIdx.x * 128;
    const int wid  = tid >> 5, lane = tid & 31;
    const int wm   = (wid >> 2) * 64;
    const int wn   = (wid & 3) * 32;

    // cp.async mapping: tile t4 (0=Ahi 1=Alo 2=Bhi 3=Blo), 2 rows per thread
    const int t4 = tid >> 6;
    const int r2 = (tid & 63) * 2;
    const bf16* gsrc;
    int gld;
    if      (t4 == 0) { gsrc = Ahi + (size_t)(m0 + r2) * lda; gld = lda; }
    else if (t4 == 1) { gsrc = Alo + (size_t)(m0 + r2) * lda; gld = lda; }
    else if (t4 == 2) { gsrc = Bhi + (size_t)(n0 + r2) * ldb; gld = ldb; }
    else              { gsrc = Blo + (size_t)(n0 + r2) * ldb; gld = ldb; }
    const uint32_t sdst0 = sbase + t4 * TILE_B + r2 * ROWB;

    // ldmatrix lane addressing
    const int a_row = (lane & 7) + ((lane >> 3) & 1) * 8;
    const int a_cb  = (lane >> 4) * 16;
    const int ll    = lane & 15;
    const int b_row = ll & 7;
    const int b_cb  = (ll >> 3) * 16;

    float acc[4][4][4];
#pragma unroll
    for (int i = 0; i < 4; i++)
#pragma unroll
        for (int j = 0; j < 4; j++)
#pragma unroll
            for (int r = 0; r < 4; r++) acc[i][j][r] = 0.f;

    const int nch = Kd >> 5;

#define HG_ISSUE(cc) do {                                                   \
        uint32_t sd = sdst0 + ((cc) & 1) * STAGE_B;                         \
        const char* gp = (const char*)gsrc + ((cc) << 6);                   \
        _Pragma("unroll")                                                   \
        for (int rr = 0; rr < 2; rr++)                                      \
            _Pragma("unroll")                                               \
            for (int ch = 0; ch < 4; ch++)                                  \
                cp16(sd + rr * ROWB + ch * 16,                              \
                     gp + (size_t)rr * gld * 2 + ch * 16);                  \
    } while (0)

    HG_ISSUE(0);
    CP_COMMIT();

    for (int c = 0; c < nch; c++) {
        if (c + 1 < nch) {
            HG_ISSUE(c + 1);
            CP_COMMIT();
            CP_WAIT1();
        } else {
            CP_WAIT0();
        }
        __syncthreads();
        const uint32_t sb = sbase + (c & 1) * STAGE_B;
#pragma unroll
        for (int ks = 0; ks < 2; ks++) {
            const int kb = ks * 32;
            uint32_t ahi4[4][4], alo4[4][4];
#pragma unroll
            for (int mf = 0; mf < 4; mf++) {
                uint32_t ad = sb + (wm + mf * 16 + a_row) * ROWB + kb + a_cb;
                ldsm4(ahi4[mf], ad);
                ldsm4(alo4[mf], ad + TILE_B);
            }
            uint32_t bhi2[4][2], blo2[4][2];
#pragma unroll
            for (int nf = 0; nf < 4; nf++) {
                uint32_t bd = sb + 2 * TILE_B + (wn + nf * 8 + b_row) * ROWB + kb + b_cb;
                ldsm2(bhi2[nf], bd);
                ldsm2(blo2[nf], bd + TILE_B);
            }
#pragma unroll
            for (int mf = 0; mf < 4; mf++)
#pragma unroll
                for (int nf = 0; nf < 4; nf++) {
                    mma16816(acc[mf][nf], ahi4[mf], bhi2[nf]);
                    mma16816(acc[mf][nf], ahi4[mf], blo2[nf]);
                    mma16816(acc[mf][nf], alo4[mf], bhi2[nf]);
                }
        }
        __syncthreads();
    }
#undef HG_ISSUE

    // epilogue
#pragma unroll
    for (int mf = 0; mf < 4; mf++) {
        int rbase = m0 + wm + mf * 16 + (lane >> 2);
#pragma unroll
        for (int nf = 0; nf < 4; nf++) {
            int cb = n0 + wn + nf * 8 + (lane & 3) * 2;
#pragma unroll
            for (int hlf = 0; hlf < 2; hlf++) {
                int row = rbase + hlf * 8;
                float vx = acc[mf][nf][hlf * 2];
                float vy = acc[mf][nf][hlf * 2 + 1];
                if (mode == 1) {
                    const float* ap = Add + (size_t)row * ldc + cb;
                    vx += ap[0]; vy += ap[1];
                }
                if (mode == 2) { vx = gelu_tanh(vx); vy = gelu_tanh(vy); }
                if (mode <= 1) {
                    *(float2*)&C[(size_t)row * ldc + cb] = make_float2(vx, vy);
                } else {
                    uint32_t h, l;
                    cvt_hilo(vx, vy, h, l);
                    *(uint32_t*)&Chi[(size_t)row * ldc + cb] = h;
                    *(uint32_t*)&Clo[(size_t)row * ldc + cb] = l;
                }
            }
        }
    }
}

// Wrappers
__global__ void __launch_bounds__(256, 2) k_hg(
    const bf16* Ahi, const bf16* Alo, int lda,
    const bf16* Bhi, const bf16* Blo, int ldb,
    float* C, const float* Add, bf16* Chi, bf16* Clo, int ldc,
    int Kd, int mode)
{
    hg_body(Ahi, Alo, lda, Bhi, Blo, ldb, C, Add, Chi, Clo, ldc, Kd, mode);
}

__global__ void __launch_bounds__(256, 2) k_hg_scores() {
    if (blockIdx.x * 128 > blockIdx.y * 128 + 127) return;  // fully masked tile
    int z = blockIdx.z;
    int b = z >> 4, h = z & 15;
    size_t qo = (size_t)b * KK * Dd + (size_t)h * HD;
    hg_body(g_qhi + qo, g_qlo + qo, Dd, g_khi + qo, g_klo + qo, Dd,
            g_scores + (size_t)z * KK * KK, nullptr, nullptr, nullptr,
            KK, HD, 0);
}

__global__ void __launch_bounds__(256, 2) k_hg_av() {
    int z = blockIdx.z;
    int b = z >> 4, h = z & 15;
    size_t po = (size_t)z * KK * KK;
    size_t vo = (size_t)z * HD * KK;
    size_t co = (size_t)b * KK * Dd + (size_t)h * HD;
    hg_body(g_phi + po, g_plo + po, KK, g_vThi + vo, g_vTlo + vo, KK,
            nullptr, nullptr, g_atthi + co, g_attlo + co, Dd, KK, 3);
}

// ----------------------------------------------------------------------------
// Weight transpose + split: W[K][N] fp32 -> Thi/Tlo[N][K] bf16
// ----------------------------------------------------------------------------
__global__ void k_tsplit(const float* __restrict__ W, bf16* __restrict__ Thi,
                         bf16* __restrict__ Tlo, int Kd, int Nd) {
    __shared__ float t[32][33];
    int k0 = blockIdx.y * 32, n0 = blockIdx.x * 32;
    int x = threadIdx.x, y = threadIdx.y;
#pragma unroll
    for (int i = 0; i < 32; i += 8)
        t[y + i][x] = W[(size_t)(k0 + y + i) * Nd + n0 + x];
    __syncthreads();
#pragma unroll
    for (int i = 0; i < 32; i += 8)
        store_hilo(Thi, Tlo, (size_t)(n0 + y + i) * Kd + k0 + x, t[x][y + i]);
}

__global__ void k_vt() {   // g_v [b][tok][h][d] -> vThi/lo [b*H+h][d][tok]
    __shared__ float t[32][33];
    int z = blockIdx.z, b = z >> 4, h = z & 15;
    int tok0 = blockIdx.x * 32, d0 = blockIdx.y * 32;
    int x = threadIdx.x, y = threadIdx.y;
#pragma unroll
    for (int i = 0; i < 32; i += 8)
        t[y + i][x] = g_v[(size_t)b * KK * Dd + (size_t)(tok0 + y + i) * Dd + h * HD + d0 + x];
    __syncthreads();
#pragma unroll
    for (int i = 0; i < 32; i += 8)
        store_hilo(g_vThi, g_vTlo,
                   (size_t)z * HD * KK + (size_t)(d0 + y + i) * KK + tok0 + x,
                   t[x][y + i]);
}

// ----------------------------------------------------------------------------
// Router / select / gather
// ----------------------------------------------------------------------------
__global__ void k_router(const float* __restrict__ hidden, const float* __restrict__ rw) {
    int wid  = (blockIdx.x * blockDim.x + threadIdx.x) >> 5;
    int lane = threadIdx.x & 31;
    if (wid >= Bb * Ss) return;
    const float4* x  = (const float4*)(hidden + (size_t)wid * Dd);
    const float4* r4 = (const float4*)rw;
    float s = 0.f;
#pragma unroll 4
    for (int i = lane; i < Dd / 4; i += 32) {
        float4 a = x[i], b = r4[i];
        s += a.x * b.x + a.y * b.y + a.z * b.z + a.w * b.w;
    }
    s = warpReduceSum(s);
    if (lane == 0) g_weights[wid] = 1.f / (1.f + expf(-s));
}

__global__ void k_select(const int* __restrict__ pos_ids) {
    __shared__ float w[Ss];
    __shared__ unsigned char sel[Ss];
    int b = blockIdx.x;
    for (int s = threadIdx.x; s < Ss; s += blockDim.x) w[s] = g_weights[b * Ss + s];
    __syncthreads();
    for (int s = threadIdx.x; s < Ss; s += blockDim.x) {
        float ws = w[s];
        int r = 0;
        for (int t = 0; t < Ss; t++) {
            float wt = w[t];
            r += (wt > ws) || (wt == ws && t < s);
        }
        sel[s] = (r < KK) ? 1 : 0;
    }
    __syncthreads();
    for (int s = threadIdx.x; s < Ss; s += blockDim.x) {
        if (sel[s]) {
            int j = 0;
            for (int t = 0; t < s; t++) j += sel[t];
            g_kidx[b * KK + j] = s;
            g_kpos[b * KK + j] = pos_ids[s];
        }
    }
}

// 256 threads/token; thread owns 8 consecutive columns -> vector stores
__global__ void k_gather_rms1(const float* __restrict__ hidden, const float* __restrict__ ln1w) {
    int t = blockIdx.x;
    int b = t >> 10;
    int s = g_kidx[t];
    const float* src = hidden + ((size_t)(b * Ss + s)) * Dd;
    float* xdst = g_X + (size_t)t * Dd;
    size_t hb = (size_t)t * Dd;
    int c0 = threadIdx.x * 8;
    float loc[8];
    *(float4*)&loc[0] = *(const float4*)&src[c0];
    *(float4*)&loc[4] = *(const float4*)&src[c0 + 4];
    float ss = 0.f;
#pragma unroll
    for (int i = 0; i < 8; i++) ss += loc[i] * loc[i];
    ss = blockReduceSum(ss);
    float r = rsqrtf(ss * (1.f / Dd) + EPSf);
    *(float4*)&xdst[c0]     = *(float4*)&loc[0];
    *(float4*)&xdst[c0 + 4] = *(float4*)&loc[4];
    float o[8];
#pragma unroll
    for (int i = 0; i < 8; i++) o[i] = loc[i] * r * ln1w[c0 + i];
    store_hilo8(g_h1hi, g_h1lo, hb + c0, o);
}

// ----------------------------------------------------------------------------
// RoPE: thread handles d-pair (2d, 2d+1) -> vector stores
// ----------------------------------------------------------------------------
__global__ void k_rope() {
    int t = blockIdx.x * blockDim.x + threadIdx.x;   // MTOT * H * 32
    if (t >= MTOT * Hh * 32) return;
    int dp  = (t & 31) * 2;
    int th  = t >> 5;
    int h   = th & 15;
    int tok = th >> 4;
    int pos = g_kpos[tok];
    float fp = (float)pos;
    float f0 = expf((float)dp       * (-9.210340371976184f / 64.f));
    float f1 = expf((float)(dp + 1) * (-9.210340371976184f / 64.f));
    float c0 = cosf(fp * f0), s0 = sinf(fp * f0);
    float c1 = cosf(fp * f1), s1 = sinf(fp * f1);
    size_t base = (size_t)tok * Dd + h * HD + dp;
    float2 q1 = *(float2*)&g_q[base];
    float2 q2 = *(float2*)&g_q[base + HALF];
    uint32_t hh, ll;
    cvt_hilo(q1.x * c0 - q2.x * s0, q1.y * c1 - q2.y * s1, hh, ll);
    *(uint32_t*)&g_qhi[base] = hh; *(uint32_t*)&g_qlo[base] = ll;
    cvt_hilo(q2.x * c0 + q1.x * s0, q2.y * c1 + q1.y * s1, hh, ll);
    *(uint32_t*)&g_qhi[base + HALF] = hh; *(uint32_t*)&g_qlo[base + HALF] = ll;
    float2 k1 = *(float2*)&g_k[base];
    float2 k2 = *(float2*)&g_k[base + HALF];
    cvt_hilo(k1.x * c0 - k2.x * s0, k1.y * c1 - k2.y * s1, hh, ll);
    *(uint32_t*)&g_khi[base] = hh; *(uint32_t*)&g_klo[base] = ll;
    cvt_hilo(k2.x * c0 + k1.x * s0, k2.y * c1 + k1.y * s1, hh, ll);
    *(uint32_t*)&g_khi[base + HALF] = hh; *(uint32_t*)&g_klo[base + HALF] = ll;
}

// ----------------------------------------------------------------------------
// Softmax: 128 threads/row, thread owns 8 consecutive columns
// ----------------------------------------------------------------------------
__global__ void k_softmax() {
    int row = blockIdx.x;
    int q = row & (KK - 1);
    const float* r = g_scores + (size_t)row * KK;
    size_t ob = (size_t)row * KK;
    int n = q + 1;
    int c0 = threadIdx.x * 8;
    float v[8];
    *(float4*)&v[0] = *(const float4*)&r[c0];
    *(float4*)&v[4] = *(const float4*)&r[c0 + 4];
    float m = -FLT_MAX;
#pragma unroll
    for (int i = 0; i < 8; i++)
        if (c0 + i < n) m = fmaxf(m, v[i]);
    m = blockReduceMax(m);
    float e[8];
    float sum = 0.f;
#pragma unroll
    for (int i = 0; i < 8; i++) {
        e[i] = (c0 + i < n) ? expf(SM_SCALE * (v[i] - m)) : 0.f;
        sum += e[i];
    }
    sum = blockReduceSum(sum);
    float inv = 1.f / sum;
#pragma unroll
    for (int i = 0; i < 8; i++) e[i] *= inv;
    store_hilo8(g_phi, g_plo, ob + c0, e);
}

// ----------------------------------------------------------------------------
// h2 = X + ao ; rmsnorm -> hi/lo (vectorized)
// ----------------------------------------------------------------------------
__global__ void k_h2rms(const float* __restrict__ ln2w) {
    int t = blockIdx.x;
    const float* xa = g_X  + (size_t)t * Dd;
    const float* ao = g_ao + (size_t)t * Dd;
    size_t ob = (size_t)t * Dd;
    int c0 = threadIdx.x * 8;
    float loc[8];
#pragma unroll
    for (int i = 0; i < 8; i += 4) {
        float4 a = *(const float4*)&xa[c0 + i];
        float4 b = *(const float4*)&ao[c0 + i];
        loc[i] = a.x + b.x; loc[i + 1] = a.y + b.y;
        loc[i + 2] = a.z + b.z; loc[i + 3] = a.w + b.w;
    }
    float ss = 0.f;
#pragma unroll
    for (int i = 0; i < 8; i++) ss += loc[i] * loc[i];
    ss = blockReduceSum(ss);
    float r = rsqrtf(ss * (1.f / Dd) + EPSf);
    float o[8];
#pragma unroll
    for (int i = 0; i < 8; i++) o[i] = loc[i] * r * ln2w[c0 + i];
    store_hilo8(g_h2nhi, g_h2nlo, ob + c0, o);
}

__global__ void k_outscale(const float* __restrict__ hidden, float* __restrict__ out) {
    size_t total4 = (size_t)Bb * Ss * Dd / 4;
    for (size_t i = (size_t)blockIdx.x * blockDim.x + threadIdx.x; i < total4;
         i += (size_t)gridDim.x * blockDim.x) {
        size_t tok = (i * 4) >> 11;
        float sc = g_weights[tok];
        float4 h = ((const float4*)hidden)[i];
        h.x *= sc; h.y *= sc; h.z *= sc; h.w *= sc;
        ((float4*)out)[i] = h;
    }
}

__global__ void k_scatter(float* __restrict__ out) {
    int t = blockIdx.x;
    int b = t >> 10;
    int s = g_kidx[t];
    int tok = b * Ss + s;
    float sc = g_weights[tok];
    float*       o  = out     + (size_t)tok * Dd;
    const float* dl = g_delta + (size_t)t * Dd;
    const float* xk = g_X     + (size_t)t * Dd;
    for (int c = threadIdx.x * 4; c < Dd; c += blockDim.x * 4) {
        float4 d4 = *(const float4*)&dl[c];
        float4 x4 = *(const float4*)&xk[c];
        *(float4*)&o[c] = make_float4(d4.x * sc + x4.x, d4.y * sc + x4.y,
                                      d4.z * sc + x4.z, d4.w * sc + x4.w);
    }
}

// ----------------------------------------------------------------------------
// Launch
// ----------------------------------------------------------------------------
extern "C" void kernel_launch(void* const* d_in, const int* in_sizes, int n_in,
                              void* d_out, int out_size) {
    const float* hidden   = (const float*)d_in[0];
    const int*   pos_ids  = (const int*)d_in[1];
    const float* router_w = (const float*)d_in[4];
    const float* ln1w     = (const float*)d_in[5];
    const float* ln2w     = (const float*)d_in[6];
    const float* Wq       = (const float*)d_in[7];
    const float* Wk       = (const float*)d_in[8];
    const float* Wv       = (const float*)d_in[9];
    const float* Wo       = (const float*)d_in[10];
    const float* W1       = (const float*)d_in[11];
    const float* W2       = (const float*)d_in[12];
    float* out = (float*)d_out;

    cudaFuncSetAttribute(k_hg,        cudaFuncAttributeMaxDynamicSharedMemorySize, HG_SMEM);
    cudaFuncSetAttribute(k_hg_scores, cudaFuncAttributeMaxDynamicSharedMemorySize, HG_SMEM);
    cudaFuncSetAttribute(k_hg_av,     cudaFuncAttributeMaxDynamicSharedMemorySize, HG_SMEM);

#define SYM(p, g) cudaGetSymbolAddress((void**)&p, g)
    bf16 *WqThi, *WqTlo, *WkThi, *WkTlo, *WvThi, *WvTlo, *WoThi, *WoTlo;
    bf16 *W1Thi, *W1Tlo, *W2Thi, *W2Tlo;
    bf16 *h1hi, *h1lo, *atthi, *attlo, *h2nhi, *h2nlo, *ffhhi, *ffhlo;
    float *q, *k, *v, *ao, *dlt;
    SYM(WqThi, g_WqThi); SYM(WqTlo, g_WqTlo);
    SYM(WkThi, g_WkThi); SYM(WkTlo, g_WkTlo);
    SYM(WvThi, g_WvThi); SYM(WvTlo, g_WvTlo);
    SYM(WoThi, g_WoThi); SYM(WoTlo, g_WoTlo);
    SYM(W1Thi, g_W1Thi); SYM(W1Tlo, g_W1Tlo);
    SYM(W2Thi, g_W2Thi); SYM(W2Tlo, g_W2Tlo);
    SYM(h1hi, g_h1hi);   SYM(h1lo, g_h1lo);
    SYM(atthi, g_atthi); SYM(attlo, g_attlo);
    SYM(h2nhi, g_h2nhi); SYM(h2nlo, g_h2nlo);
    SYM(ffhhi, g_ffhhi); SYM(ffhlo, g_ffhlo);
    SYM(q, g_q); SYM(k, g_k); SYM(v, g_v);
    SYM(ao, g_ao); SYM(dlt, g_delta);
#undef SYM

    dim3 tb(32, 8);
    k_tsplit<<<dim3(Dd / 32, Dd / 32), tb>>>(Wq, WqThi, WqTlo, Dd, Dd);
    k_tsplit<<<dim3(Dd / 32, Dd / 32), tb>>>(Wk, WkThi, WkTlo, Dd, Dd);
    k_tsplit<<<dim3(Dd / 32, Dd / 32), tb>>>(Wv, WvThi, WvTlo, Dd, Dd);
    k_tsplit<<<dim3(Dd / 32, Dd / 32), tb>>>(Wo, WoThi, WoTlo, Dd, Dd);
    k_tsplit<<<dim3(FFd / 32, Dd / 32), tb>>>(W1, W1Thi, W1Tlo, Dd, FFd);
    k_tsplit<<<dim3(Dd / 32, FFd / 32), tb>>>(W2, W2Thi, W2Tlo, FFd, Dd);

    k_router<<<(Bb * Ss) / 8, 256>>>(hidden, router_w);
    k_select<<<Bb, 1024>>>(pos_ids);
    k_gather_rms1<<<MTOT, 256>>>(hidden, ln1w);

    dim3 gD(Dd / 128, MTOT / 128);
    k_hg<<<gD, 256, HG_SMEM>>>(h1hi, h1lo, Dd, WqThi, WqTlo, Dd,
                               q, nullptr, nullptr, nullptr, Dd, Dd, 0);
    k_hg<<<gD, 256, HG_SMEM>>>(h1hi, h1lo, Dd, WkThi, WkTlo, Dd,
                               k, nullptr, nullptr, nullptr, Dd, Dd, 0);
    k_hg<<<gD, 256, HG_SMEM>>>(h1hi, h1lo, Dd, WvThi, WvTlo, Dd,
                               v, nullptr, nullptr, nullptr, Dd, Dd, 0);

    k_rope<<<(MTOT * Hh * 32 + 255) / 256, 256>>>();
    k_vt<<<dim3(KK / 32, HD / 32, BH), tb>>>();
    k_hg_scores<<<dim3(KK / 128, KK / 128, BH), 256, HG_SMEM>>>();
    k_softmax<<<BH * KK, 128>>>();
    k_hg_av<<<dim3(1, KK / 128, BH), 256, HG_SMEM>>>();

    k_hg<<<gD, 256, HG_SMEM>>>(atthi, attlo, Dd, WoThi, WoTlo, Dd,
                               ao, nullptr, nullptr, nullptr, Dd, Dd, 0);
    k_h2rms<<<MTOT, 256>>>(ln2w);
    k_hg<<<dim3(FFd / 128, MTOT / 128), 256, HG_SMEM>>>(
        h2nhi, h2nlo, Dd, W1Thi, W1Tlo, Dd,
        nullptr, nullptr, ffhhi, ffhlo, FFd, Dd, 2);
    k_hg<<<gD, 256, HG_SMEM>>>(ffhhi, ffhlo, FFd, W2Thi, W2Tlo, FFd,
                               dlt, ao, nullptr, nullptr, Dd, FFd, 1);

    k_outscale<<<8192, 256>>>(hidden, out);
    k_scatter<<<MTOT, 256>>>(out);
}